// round 15
// baseline (speedup 1.0000x reference)
#include <cuda_runtime.h>

#define BB 64
#define NN 128
#define FF 4
#define HH 100
#define HHP 104
#define NQ 25            // HH/4 quads
#define PP 8128          // NN*(NN-1)/2

typedef unsigned long long u64;

// folded weights (written by k_fold, read by k_pairs)
__device__ __align__(16) float g_M1[FF * HHP];
__device__ __align__(16) float g_M2[FF * HHP];
__device__ __align__(16) float g_c2[HHP];

// packed 2-dim pair op: acc += max(a+b, 0) * w   (both f32 halves)
__device__ __forceinline__ void pd2(u64 a, u64 b, u64 w, u64& acc) {
    asm("{\n\t"
        ".reg .b64 t;\n\t"
        ".reg .f32 lo, hi;\n\t"
        "add.rn.f32x2 t, %1, %2;\n\t"
        "mov.b64 {lo, hi}, t;\n\t"
        "max.f32 lo, lo, 0f00000000;\n\t"
        "max.f32 hi, hi, 0f00000000;\n\t"
        "mov.b64 t, {lo, hi};\n\t"
        "fma.rn.f32x2 %0, t, %3, %0;\n\t"
        "}" : "+l"(acc) : "l"(a), "l"(b), "l"(w));
}

__device__ __forceinline__ float2 unpk(u64 t) {
    float2 f;
    asm("mov.b64 {%0, %1}, %2;" : "=f"(f.x), "=f"(f.y) : "l"(t));
    return f;
}

// ---------------------------------------------------------------- K1: fold (one block)
__global__ void __launch_bounds__(512) k_fold(const float* __restrict__ W1,
                                              const float* __restrict__ b1,
                                              const float* __restrict__ W2,
                                              const float* __restrict__ b2) {
    __shared__ float sW1T[HH * 8];        // [k][f] transposed
    __shared__ float sb1[HH];
    __shared__ float sPart[500 * 9];
    const int tid = threadIdx.x;

    for (int i = tid; i < 2 * FF * HH; i += 512) {
        int f = i / HH, k = i % HH;
        sW1T[k * 8 + f] = W1[i];
    }
    if (tid < HH) sb1[tid] = b1[tid];
    __syncthreads();

    if (tid < 500) {
        const int d  = tid % HH;
        const int kc = tid / HH;
        float m[9];
        #pragma unroll
        for (int i = 0; i < 9; ++i) m[i] = 0.f;
        #pragma unroll 5
        for (int kk = 0; kk < 20; ++kk) {
            int k = kc * 20 + kk;
            float w = W2[k * HH + d];
            float4 wa = *(const float4*)(sW1T + k * 8);
            float4 wb = *(const float4*)(sW1T + k * 8 + 4);
            m[0] = fmaf(wa.x, w, m[0]); m[1] = fmaf(wa.y, w, m[1]);
            m[2] = fmaf(wa.z, w, m[2]); m[3] = fmaf(wa.w, w, m[3]);
            m[4] = fmaf(wb.x, w, m[4]); m[5] = fmaf(wb.y, w, m[5]);
            m[6] = fmaf(wb.z, w, m[6]); m[7] = fmaf(wb.w, w, m[7]);
            m[8] = fmaf(sb1[k], w, m[8]);
        }
        #pragma unroll
        for (int i = 0; i < 9; ++i) sPart[tid * 9 + i] = m[i];
    }
    __syncthreads();

    if (tid < HH) {
        float s[9];
        #pragma unroll
        for (int i = 0; i < 9; ++i) s[i] = 0.f;
        #pragma unroll
        for (int kc = 0; kc < 5; ++kc)
            #pragma unroll
            for (int i = 0; i < 9; ++i)
                s[i] += sPart[(kc * HH + tid) * 9 + i];
        #pragma unroll
        for (int f = 0; f < FF; ++f) { g_M1[f * HHP + tid] = s[f]; g_M2[f * HHP + tid] = s[4 + f]; }
        g_c2[tid] = s[8] + b2[tid];
    }
    // make g_* visible, then allow the dependent grid to pass its sync point
    __syncthreads();
    __threadfence();
    cudaTriggerProgrammaticLaunchCompletion();
}

__device__ __forceinline__ int j_of(int g) { return (g < 8) ? 0 : (g < 24) ? 1 : (g < 48) ? 2 : 3; }
__device__ __forceinline__ int i0_of(int g, int j) {
    int base = (j == 0) ? 0 : (j == 1) ? 8 : (j == 2) ? 24 : 48;
    return (g - base) * 4;
}

// ---------------------------------------------------------------- K2: fused transform + pairs
// Block = (batch, blk4): 4 consecutive tiles of the 80-tile list (one strip,
// 16 contiguous A-rows). One 4x32 tile per warp; packed f32x2 inner math.
// Folded weights read straight from global (L1-resident) — no smem staging.
__global__ void __launch_bounds__(128, 10)
k_pairs(const float* __restrict__ x,
        const float* __restrict__ W3, const float* __restrict__ b3p,
        float* __restrict__ out) {
    __shared__ __align__(16) float  sA[16 * HHP];      // 6656 B
    __shared__ __align__(16) float4 sB4[NQ * 32];      // 12800 B
    __shared__ __align__(16) float  sW3[HHP];          // 416 B

    const int tid  = threadIdx.x;
    const int warp = tid >> 5;
    const int lane = tid & 31;
    const int b    = blockIdx.x / 20;
    const int blk4 = blockIdx.x % 20;

    const int g0     = blk4 * 4;           // first tile of this block
    const int j      = j_of(g0);
    const int J0     = j * 32;
    const int row_lo = i0_of(g0, j);       // 16 contiguous rows start here

    // ---- phase 0 (independent of k_fold): W3 -------------------------------
    if (tid < NQ) *(float4*)(sW3 + tid * 4) = ((const float4*)W3)[tid];

    // wait for k_fold's g_M1/g_M2/g_c2
    cudaGridDependencySynchronize();

    // ---- phase 1a: A rows [row_lo, row_lo+16), c2 folded in ----------------
    for (int it = tid; it < 16 * NQ; it += 128) {
        int r = it / NQ, q = it % NQ, d0 = q * 4;
        float4 xv = *(const float4*)(x + (b * NN + row_lo + r) * FF);
        float4 a  = *(const float4*)(g_c2 + d0);
        #pragma unroll
        for (int f = 0; f < FF; ++f) {
            float xf = (f == 0) ? xv.x : (f == 1) ? xv.y : (f == 2) ? xv.z : xv.w;
            float4 m1 = *(const float4*)(g_M1 + f * HHP + d0);
            a.x = fmaf(xf, m1.x, a.x); a.y = fmaf(xf, m1.y, a.y);
            a.z = fmaf(xf, m1.z, a.z); a.w = fmaf(xf, m1.w, a.w);
        }
        *(float4*)(sA + r * HHP + d0) = a;
    }
    // ---- phase 1b: B strip cols [J0, J0+32) --------------------------------
    for (int it = tid; it < 32 * NQ; it += 128) {
        int col = it & 31, q = it >> 5, d0 = q * 4;
        float4 xv = *(const float4*)(x + (b * NN + J0 + col) * FF);
        float4 v  = make_float4(0.f, 0.f, 0.f, 0.f);
        #pragma unroll
        for (int f = 0; f < FF; ++f) {
            float xf = (f == 0) ? xv.x : (f == 1) ? xv.y : (f == 2) ? xv.z : xv.w;
            float4 m2 = *(const float4*)(g_M2 + f * HHP + d0);
            v.x = fmaf(xf, m2.x, v.x); v.y = fmaf(xf, m2.y, v.y);
            v.z = fmaf(xf, m2.z, v.z); v.w = fmaf(xf, m2.w, v.w);
        }
        sB4[q * 32 + col] = v;
    }
    __syncthreads();

    // ---- phase 2: one 4x32 tile per warp, packed f32x2 math ----------------
    const int r0 = warp * 4;               // local row of tile
    const int I0 = row_lo + r0;
    const int i2 = J0 + lane;
    const float b3 = b3p[0];

    const ulonglong2* A0 = (const ulonglong2*)(sA + (r0 + 0) * HHP);
    const ulonglong2* A1 = (const ulonglong2*)(sA + (r0 + 1) * HHP);
    const ulonglong2* A2 = (const ulonglong2*)(sA + (r0 + 2) * HHP);
    const ulonglong2* A3 = (const ulonglong2*)(sA + (r0 + 3) * HHP);
    const ulonglong2* Bp = (const ulonglong2*)sB4 + lane;
    const ulonglong2* Wp = (const ulonglong2*)sW3;

    u64 acc0 = 0ull, acc1 = 0ull, acc2 = 0ull, acc3 = 0ull;
    #pragma unroll 5
    for (int q = 0; q < NQ; ++q) {
        ulonglong2 a0 = A0[q];
        ulonglong2 a1 = A1[q];
        ulonglong2 a2 = A2[q];
        ulonglong2 a3 = A3[q];
        ulonglong2 w  = Wp[q];
        ulonglong2 bq = Bp[q * 32];

        pd2(a0.x, bq.x, w.x, acc0);
        pd2(a1.x, bq.x, w.x, acc1);
        pd2(a2.x, bq.x, w.x, acc2);
        pd2(a3.x, bq.x, w.x, acc3);

        pd2(a0.y, bq.y, w.y, acc0);
        pd2(a1.y, bq.y, w.y, acc1);
        pd2(a2.y, bq.y, w.y, acc2);
        pd2(a3.y, bq.y, w.y, acc3);
    }

    float2 f0 = unpk(acc0), f1 = unpk(acc1), f2 = unpk(acc2), f3 = unpk(acc3);
    float zs[4] = {f0.x + f0.y, f1.x + f1.y, f2.x + f2.y, f3.x + f3.y};
    #pragma unroll
    for (int t = 0; t < 4; ++t) {
        int i1 = I0 + t;
        if (i1 < i2) {
            float z = zs[t] + b3;
            float s = 1.f / (1.f + __expf(-z));
            int p = i1 * (2 * NN - 1 - i1) / 2 + (i2 - i1 - 1);
            out[b * PP + p] = s;
        }
    }
}

// ---------------------------------------------------------------- launch
extern "C" void kernel_launch(void* const* d_in, const int* in_sizes, int n_in,
                              void* d_out, int out_size) {
    const float* x  = (const float*)d_in[0];
    // d_in[1] = in_hitnr (unused by reference)
    const float* W1 = (const float*)d_in[2];
    const float* b1 = (const float*)d_in[3];
    const float* W2 = (const float*)d_in[4];
    const float* b2 = (const float*)d_in[5];
    const float* W3 = (const float*)d_in[6];
    const float* b3 = (const float*)d_in[7];
    float* out = (float*)d_out;

    k_fold<<<1, 512>>>(W1, b1, W2, b2);

    // k_pairs with programmatic dependent launch (overlaps with k_fold).
    cudaLaunchConfig_t cfg = {};
    cfg.gridDim  = dim3(BB * 20, 1, 1);
    cfg.blockDim = dim3(128, 1, 1);
    cudaLaunchAttribute attr[1];
    attr[0].id = cudaLaunchAttributeProgrammaticStreamSerialization;
    attr[0].val.programmaticStreamSerializationAllowed = 1;
    cfg.attrs = attr;
    cfg.numAttrs = 1;
    cudaError_t err = cudaLaunchKernelEx(&cfg, k_pairs, x, W3, b3, out);
    if (err != cudaSuccess) {
        // fallback: plain stream-ordered launch (gridDependencySynchronize is
        // trivially satisfied when not PDL-launched)
        k_pairs<<<BB * 20, 128>>>(x, W3, b3, out);
    }
}